// round 3
// baseline (speedup 1.0000x reference)
#include <cuda_runtime.h>
#include <math.h>
#include <stdint.h>

#define H 2048
#define G 8192
#define NBQ 8
#define NBLK 148
#define NTH 448
#define WPB 14
#define NW_ALL (NBLK*WPB)        // 2072 warps, all blocks
// gate/attn warps live in blocks 1..147 -> 2058 warps >= 2048

// ---------------- device state (scratch; no allocations) ----------------
__device__ float d_xproj[18][G];   // row0 zeros, 1..9 enc proj, 10..17 anchor proj
__device__ float d_bsum[G];
__device__ float d_c[H];
__device__ float d_hb[2][H];
__device__ float d_aw1[10][H];
__device__ float d_part[10][H];    // per-t logit partials
__device__ int   d_xrow;
__device__ unsigned g_count = 0;
__device__ unsigned g_flag  = 0;   // monotonic across launches
__device__ unsigned d_sflag = 0;   // monotonic sample-publication flag
__device__ unsigned d_k0, d_k1;
__device__ float d_lp, d_ent;

struct P {
  const float *enc,*wih,*bih,*whh,*bhh,*wsoft,*bsoft,*bsnl,*w1,*w2,*v;
  float* out;
};

// ---------------- scoped atomics ----------------
__device__ __forceinline__ unsigned atomAddRel(unsigned* p, unsigned v){
  unsigned old;
  asm volatile("atom.add.release.gpu.global.u32 %0,[%1],%2;"
               : "=r"(old) : "l"(p), "r"(v) : "memory");
  return old;
}
__device__ __forceinline__ unsigned ldAcq(unsigned* p){
  unsigned v;
  asm volatile("ld.acquire.gpu.global.u32 %0,[%1];" : "=r"(v) : "l"(p) : "memory");
  return v;
}
__device__ __forceinline__ void stRel(unsigned* p, unsigned v){
  asm volatile("st.release.gpu.global.u32 [%0],%1;" :: "l"(p), "r"(v) : "memory");
}
__device__ __forceinline__ void stRelax(unsigned* p, unsigned v){
  asm volatile("st.relaxed.gpu.global.u32 [%0],%1;" :: "l"(p), "r"(v) : "memory");
}

// ---------------- grid barrier ----------------
__device__ __forceinline__ void gsync(unsigned &gen){
  __syncthreads();
  if (threadIdx.x == 0){
    unsigned target = gen + 1u;
    unsigned old = atomAddRel(&g_count, 1u);
    if (old == (unsigned)(NBLK - 1)){
      stRelax(&g_count, 0u);
      stRel(&g_flag, target);
    } else {
      unsigned v;
      do { v = ldAcq(&g_flag); } while ((int)(v - target) < 0);
    }
  }
  gen += 1u;
  __syncthreads();
}

// ---------------- threefry2x32 (JAX) ----------------
__device__ __forceinline__ void tf2(unsigned k0, unsigned k1, unsigned x0, unsigned x1,
                                    unsigned &o0, unsigned &o1){
  unsigned ks2 = k0 ^ k1 ^ 0x1BD11BDAu;
  x0 += k0; x1 += k1;
#define RND(r) { x0 += x1; x1 = (x1<<(r))|(x1>>(32-(r))); x1 ^= x0; }
  RND(13) RND(15) RND(26) RND(6)   x0 += k1;  x1 += ks2 + 1u;
  RND(17) RND(29) RND(16) RND(24)  x0 += ks2; x1 += k0  + 2u;
  RND(13) RND(15) RND(26) RND(6)   x0 += k0;  x1 += k1  + 3u;
  RND(17) RND(29) RND(16) RND(24)  x0 += k1;  x1 += ks2 + 4u;
  RND(13) RND(15) RND(26) RND(6)   x0 += ks2; x1 += k0  + 5u;
#undef RND
  o0 = x0; o1 = x1;
}

// partitionable-threefry split + random_bits + gumbel-argmax + lp/entropy
__device__ int do_sample(int n, const float* lg){
  unsigned nk0, nk1, s0, s1;
  tf2(d_k0, d_k1, 0u, 0u, nk0, nk1);
  tf2(d_k0, d_k1, 0u, 1u, s0,  s1);
  d_k0 = nk0; d_k1 = nk1;
  const float TINY = 1.17549435e-38f;
  float best = -INFINITY; int bi = 0;
  for (int i = 0; i < n; i++){
    unsigned o0, o1;
    tf2(s0, s1, 0u, (unsigned)i, o0, o1);
    unsigned bits = o0 ^ o1;
    float f = __uint_as_float((bits >> 9) | 0x3f800000u) - 1.0f;
    float u = fmaxf(TINY, f * (1.0f - TINY) + TINY);
    float z = -logf(-logf(u)) + lg[i];
    if (z > best){ best = z; bi = i; }
  }
  float mx = lg[0];
  for (int i = 1; i < n; i++) mx = fmaxf(mx, lg[i]);
  float se = 0.f;
  for (int i = 0; i < n; i++) se += expf(lg[i] - mx);
  float lse = logf(se);
  d_lp += -(lg[bi] - mx - lse);
  float e = 0.f;
  for (int i = 0; i < n; i++){ float ls = lg[i] - mx - lse; e -= ls * expf(ls); }
  d_ent += e;
  return bi;
}

__device__ __forceinline__ float sigf(float x){ return 1.f / (1.f + expf(-x)); }

__device__ __forceinline__ float wdot(const float* __restrict__ w,
                                      const float* __restrict__ shv, int lane){
  const float4* w4 = (const float4*)w;
  const float4* h4 = (const float4*)shv;
  float a = 0.f;
#pragma unroll
  for (int t = 0; t < 16; t++){
    float4 wv = w4[lane + 32*t];
    float4 hv = h4[lane + 32*t];
    a += wv.x*hv.x; a += wv.y*hv.y; a += wv.z*hv.z; a += wv.w*hv.w;
  }
#pragma unroll
  for (int o = 16; o; o >>= 1) a += __shfl_xor_sync(0xffffffffu, a, o);
  return a;
}

__device__ __forceinline__ void load_h_smem(float* sh, const float* hsrc){
  for (int i = threadIdx.x; i < H; i += NTH) sh[i] = __ldcg(hsrc + i);
  __syncthreads();
}

// ---------------- cell (blocks 1..147). xrow<0 => spin on sample flag ----------------
__device__ void cell_work(const P& p, int xrow, unsigned need_seq,
                          int hp, float* sh, int gwc, int lane){
  load_h_smem(sh, d_hb[hp]);
  int j = gwc;
  if (j < H){
    const float4* h4 = (const float4*)sh;
    const float4* w0 = (const float4*)(p.whh + (size_t)j        * H);
    const float4* w1 = (const float4*)(p.whh + (size_t)(j + H)  * H);
    const float4* w2 = (const float4*)(p.whh + (size_t)(j + 2*H)* H);
    const float4* w3 = (const float4*)(p.whh + (size_t)(j + 3*H)* H);
    float a0=0.f, a1=0.f, a2=0.f, a3=0.f;
#pragma unroll
    for (int t = 0; t < 16; t++){
      float4 hv = h4[lane + 32*t];
      float4 x0 = w0[lane + 32*t];
      float4 x1 = w1[lane + 32*t];
      float4 x2 = w2[lane + 32*t];
      float4 x3 = w3[lane + 32*t];
      a0 += x0.x*hv.x + x0.y*hv.y + x0.z*hv.z + x0.w*hv.w;
      a1 += x1.x*hv.x + x1.y*hv.y + x1.z*hv.z + x1.w*hv.w;
      a2 += x2.x*hv.x + x2.y*hv.y + x2.z*hv.z + x2.w*hv.w;
      a3 += x3.x*hv.x + x3.y*hv.y + x3.z*hv.z + x3.w*hv.w;
    }
#pragma unroll
    for (int o = 16; o; o >>= 1){
      a0 += __shfl_xor_sync(0xffffffffu, a0, o);
      a1 += __shfl_xor_sync(0xffffffffu, a1, o);
      a2 += __shfl_xor_sync(0xffffffffu, a2, o);
      a3 += __shfl_xor_sync(0xffffffffu, a3, o);
    }
    if (lane == 0){
      int xr = xrow;
      if (xr < 0){
        unsigned v;
        do { v = ldAcq(&d_sflag); } while ((int)(v - need_seq) < 0);
        xr = *((volatile int*)&d_xrow);
      }
      const float* xp = d_xproj[xr];
      float gi = a0 + __ldcg(xp + j)       + d_bsum[j];
      float gf = a1 + __ldcg(xp + j + H)   + d_bsum[j + H];
      float gg = a2 + __ldcg(xp + j + 2*H) + d_bsum[j + 2*H];
      float go = a3 + __ldcg(xp + j + 3*H) + d_bsum[j + 3*H];
      float c2 = sigf(gf) * d_c[j] + sigf(gi) * tanhf(gg);
      float h2 = sigf(go) * tanhf(c2);
      d_c[j] = c2;
      d_hb[hp ^ 1][j] = h2;
    }
  }
}

// ---------------- attn: hw2[t] + logit partials (blocks 1..147) ----------------
__device__ void attn_work(const P& p, int hp, int L, float* sh, int gwc, int lane){
  load_h_smem(sh, d_hb[hp]);
  int t = gwc;
  if (t < H){
    float s = wdot(p.w2 + (size_t)t * H, sh, lane);
    if (lane == 0){
      float vt = p.v[t];
#pragma unroll 4
      for (int i = 0; i < L; i++)
        d_part[i][t] = tanhf(__ldcg(&d_aw1[i][t]) + s) * vt;
    }
  }
}

// ---------------- proj (all blocks): optional W_ih anchor row + aw1 row ----------------
__device__ void proj_work(const P& p, int hp, int arow, int aidx, float* sh,
                          int gwa, int lane){
  load_h_smem(sh, d_hb[hp]);
  if (arow >= 0){
    for (int r = gwa; r < G; r += NW_ALL){
      float s = wdot(p.wih + (size_t)r * H, sh, lane);
      if (lane == 0) d_xproj[arow][r] = s;
    }
  }
  if (gwa < H){
    float s = wdot(p.w1 + (size_t)gwa * H, sh, lane);
    if (lane == 0) d_aw1[aidx][gwa] = s;
  }
}

// ---------------- block-0 sample work (runs concurrently with next cell) ----------------
__device__ void b0_idx(const P& p, int L, int arcpos, float* sh, unsigned pub){
  int wi = threadIdx.x >> 5, lane = threadIdx.x & 31;
  if (wi < L){
    float a = 0.f;
    for (int t = lane; t < H; t += 32) a += __ldcg(&d_part[wi][t]);
#pragma unroll
    for (int o = 16; o; o >>= 1) a += __shfl_xor_sync(0xffffffffu, a, o);
    if (lane == 0) sh[wi] = a;
  }
  __syncthreads();
  if (threadIdx.x == 0){
    float lg[10];
    for (int i = 0; i < L; i++) lg[i] = 2.5f * tanhf(sh[i] / 5.0f);
    int idx = do_sample(L, lg);
    d_xrow = (idx < 2) ? 0 : (10 + idx - 2);
    p.out[arcpos] = (float)idx;
    stRel(&d_sflag, pub);
  }
}

__device__ void b0_op(const P& p, int hp, int use_bias, int arcpos, float* sh,
                      unsigned pub){
  int wi = threadIdx.x >> 5, lane = threadIdx.x & 31;
  if (wi < NBQ){
    const float* hc = d_hb[hp];
    float a = 0.f;
    for (int t = lane; t < H; t += 32) a += p.wsoft[wi * H + t] * __ldcg(hc + t);
#pragma unroll
    for (int o = 16; o; o >>= 1) a += __shfl_xor_sync(0xffffffffu, a, o);
    if (lane == 0) sh[wi] = a;
  }
  __syncthreads();
  if (threadIdx.x == 0){
    float lg[NBQ];
    for (int i = 0; i < NBQ; i++){
      lg[i] = tanhf((sh[i] + p.bsoft[i]) / 5.0f);
      if (use_bias) lg[i] += p.bsnl[i];
    }
    int op = do_sample(NBQ, lg);
    d_xrow = 2 + op;
    p.out[arcpos] = (float)op;
    stRel(&d_sflag, pub);
  }
}

__global__ void __launch_bounds__(NTH, 1) ctrl_kernel(P p){
  extern __shared__ float sh[];
  int tid = threadIdx.x, wi = tid >> 5, lane = tid & 31;
  int b = blockIdx.x;
  unsigned gen   = *((volatile unsigned*)&g_flag);
  unsigned sbase = *((volatile unsigned*)&d_sflag);
  unsigned sc = 0;                      // samples published so far
  int gwa = b * WPB + wi;               // all-block warp id
  int gwc = (b == 0) ? H : (b - 1) * WPB + wi;  // gate/attn warp id (block0 inactive)

  // ---- init ----
  for (int i = b*NTH + tid; i < H; i += NBLK*NTH){
    d_c[i] = 0.f; d_hb[0][i] = 0.f; d_hb[1][i] = 0.f;
  }
  for (int i = b*NTH + tid; i < G; i += NBLK*NTH){
    d_bsum[i] = p.bih[i] + p.bhh[i];
    d_xproj[0][i] = 0.f;
  }
  if (b == 0 && tid == 0){
    d_k0 = 0u; d_k1 = 42u;
    d_lp = 0.f; d_ent = 0.f;
  }
  // encoder rows -> smem, project all 9 through W_ih (all blocks)
  for (int i = tid; i < 9*H; i += NTH) sh[i] = p.enc[i];
  __syncthreads();
  for (int r = gwa; r < G; r += NW_ALL){
    const float4* w4 = (const float4*)(p.wih + (size_t)r * H);
    float acc[9];
#pragma unroll
    for (int e = 0; e < 9; e++) acc[e] = 0.f;
    for (int t = 0; t < 16; t++){
      float4 wv = w4[lane + 32*t];
#pragma unroll
      for (int e = 0; e < 9; e++){
        float4 xv = ((const float4*)sh)[e*512 + lane + 32*t];
        acc[e] += wv.x*xv.x + wv.y*xv.y + wv.z*xv.z + wv.w*xv.w;
      }
    }
    for (int e = 0; e < 9; e++){
      float a = acc[e];
#pragma unroll
      for (int o = 16; o; o >>= 1) a += __shfl_xor_sync(0xffffffffu, a, o);
      if (lane == 0) d_xproj[1 + e][r] = a;
    }
  }
  gsync(gen);

  // ---- two sampler runs ----
  int hp = 0;
  for (int smp = 0; smp < 2; smp++){
    int ab = smp * 32;
    int ub = (smp == 0);
    for (int t = 0; t < 2; t++){
      if (b > 0) cell_work(p, 1, 0, hp, sh, gwc, lane);   // input = enc[0]
      hp ^= 1; gsync(gen);
      proj_work(p, hp, -1, t, sh, gwa, lane);             // aw1[t] only
      gsync(gen);
    }
    for (int L = 2; L <= 9; L++){
      int base = ab + (L - 2) * 4;
      // --- idx0: cell(static enc0), attn ---
      if (b > 0) cell_work(p, 1, 0, hp, sh, gwc, lane);
      hp ^= 1; gsync(gen);
      if (b > 0) attn_work(p, hp, L, sh, gwc, lane);
      gsync(gen);
      // --- idx1 cell  ||  block0 samples idx0 ---
      sc++;
      if (b == 0) b0_idx(p, L, base + 0, sh, sbase + sc);
      else cell_work(p, -1, sbase + sc, hp, sh, gwc, lane);
      hp ^= 1; gsync(gen);
      if (b > 0) attn_work(p, hp, L, sh, gwc, lane);
      gsync(gen);
      // --- op0 cell  ||  block0 samples idx1 ---
      sc++;
      if (b == 0) b0_idx(p, L, base + 2, sh, sbase + sc);
      else cell_work(p, -1, sbase + sc, hp, sh, gwc, lane);
      hp ^= 1; gsync(gen);
      // --- op1 cell  ||  block0 samples op0 (logits from h of op0 cell = d_hb[hp]) ---
      sc++;
      if (b == 0) b0_op(p, hp, ub, base + 1, sh, sbase + sc);
      else cell_work(p, -1, sbase + sc, hp, sh, gwc, lane);
      hp ^= 1; gsync(gen);
      // --- anchor cell  ||  block0 samples op1 ---
      sc++;
      if (b == 0) b0_op(p, hp, ub, base + 3, sh, sbase + sc);
      else cell_work(p, -1, sbase + sc, hp, sh, gwc, lane);
      hp ^= 1; gsync(gen);
      // --- anchor projection (all blocks) ---
      proj_work(p, hp, 10 + (L - 2), L, sh, gwa, lane);
      gsync(gen);
    }
  }

  if (b == 0 && tid == 0){
    p.out[64] = d_lp;
    p.out[65] = d_ent;
  }
}

extern "C" void kernel_launch(void* const* d_in, const int* in_sizes, int n_in,
                              void* d_out, int out_size){
  P p;
  p.enc   = (const float*)d_in[0];
  p.wih   = (const float*)d_in[1];
  p.bih   = (const float*)d_in[2];
  p.whh   = (const float*)d_in[3];
  p.bhh   = (const float*)d_in[4];
  p.wsoft = (const float*)d_in[5];
  p.bsoft = (const float*)d_in[6];
  p.bsnl  = (const float*)d_in[7];
  p.w1    = (const float*)d_in[8];
  p.w2    = (const float*)d_in[9];
  p.v     = (const float*)d_in[10];
  p.out   = (float*)d_out;
  (void)in_sizes; (void)n_in; (void)out_size;

  size_t smem = 9 * H * sizeof(float);
  cudaFuncSetAttribute(ctrl_kernel, cudaFuncAttributeMaxDynamicSharedMemorySize, (int)smem);
  ctrl_kernel<<<NBLK, NTH, smem>>>(p);
}

// round 4
// speedup vs baseline: 1.0597x; 1.0597x over previous
#include <cuda_runtime.h>
#include <math.h>
#include <stdint.h>

#define H 2048
#define G 8192
#define NBQ 8
#define NBLK 148
#define NTH 448
#define WPB 14
#define NW_ALL (NBLK*WPB)   // 2072 warps (proj work, all blocks)
// gate/attn rows handled by blocks 1..147 (2058 warps >= 2048); block 0 = control

// ---------------- device state ----------------
__device__ float d_xproj[18][G];   // 0 zeros, 1..9 enc proj, 10..17 anchor proj
__device__ float d_bsum[G];
__device__ float d_c[H];
__device__ float d_hb[2][H];
__device__ float d_aw1[10][H];
__device__ float d_blkpart[10][160];  // [logit][block-1]
__device__ int   d_xrow;
__device__ unsigned g_count = 0;
__device__ unsigned g_flag  = 0;   // monotonic across graph replays
__device__ unsigned d_sflag = 0;   // monotonic sample flag
__device__ unsigned d_acnt  = 0;   // monotonic attn-partial counter
__device__ unsigned d_k0, d_k1;
__device__ float d_lp, d_ent;

struct P {
  const float *enc,*wih,*bih,*whh,*bhh,*wsoft,*bsoft,*bsnl,*w1,*w2,*v;
  float* out;
};

// ---------------- scoped atomics ----------------
__device__ __forceinline__ unsigned atomAddRel(unsigned* p, unsigned v){
  unsigned old;
  asm volatile("atom.add.release.gpu.global.u32 %0,[%1],%2;"
               : "=r"(old) : "l"(p), "r"(v) : "memory");
  return old;
}
__device__ __forceinline__ unsigned ldAcq(unsigned* p){
  unsigned v;
  asm volatile("ld.acquire.gpu.global.u32 %0,[%1];" : "=r"(v) : "l"(p) : "memory");
  return v;
}
__device__ __forceinline__ void stRel(unsigned* p, unsigned v){
  asm volatile("st.release.gpu.global.u32 [%0],%1;" :: "l"(p), "r"(v) : "memory");
}
__device__ __forceinline__ void stRelax(unsigned* p, unsigned v){
  asm volatile("st.relaxed.gpu.global.u32 [%0],%1;" :: "l"(p), "r"(v) : "memory");
}

// ---------------- grid barrier ----------------
__device__ __forceinline__ void gsync(unsigned &gen){
  __syncthreads();
  if (threadIdx.x == 0){
    unsigned target = gen + 1u;
    unsigned old = atomAddRel(&g_count, 1u);
    if (old == (unsigned)(NBLK - 1)){
      stRelax(&g_count, 0u);
      stRel(&g_flag, target);
    } else {
      unsigned v;
      do { v = ldAcq(&g_flag); } while ((int)(v - target) < 0);
    }
  }
  gen += 1u;
  __syncthreads();
}

// ---------------- threefry2x32 (JAX partitionable) ----------------
__device__ __forceinline__ void tf2(unsigned k0, unsigned k1, unsigned x0, unsigned x1,
                                    unsigned &o0, unsigned &o1){
  unsigned ks2 = k0 ^ k1 ^ 0x1BD11BDAu;
  x0 += k0; x1 += k1;
#define RND(r) { x0 += x1; x1 = (x1<<(r))|(x1>>(32-(r))); x1 ^= x0; }
  RND(13) RND(15) RND(26) RND(6)   x0 += k1;  x1 += ks2 + 1u;
  RND(17) RND(29) RND(16) RND(24)  x0 += ks2; x1 += k0  + 2u;
  RND(13) RND(15) RND(26) RND(6)   x0 += k0;  x1 += k1  + 3u;
  RND(17) RND(29) RND(16) RND(24)  x0 += k1;  x1 += ks2 + 4u;
  RND(13) RND(15) RND(26) RND(6)   x0 += ks2; x1 += k0  + 5u;
#undef RND
  o0 = x0; o1 = x1;
}

__device__ int do_sample(int n, const float* lg){
  unsigned nk0, nk1, s0, s1;
  tf2(d_k0, d_k1, 0u, 0u, nk0, nk1);
  tf2(d_k0, d_k1, 0u, 1u, s0,  s1);
  d_k0 = nk0; d_k1 = nk1;
  const float TINY = 1.17549435e-38f;
  float best = -INFINITY; int bi = 0;
  for (int i = 0; i < n; i++){
    unsigned o0, o1;
    tf2(s0, s1, 0u, (unsigned)i, o0, o1);
    unsigned bits = o0 ^ o1;
    float f = __uint_as_float((bits >> 9) | 0x3f800000u) - 1.0f;
    float u = fmaxf(TINY, f * (1.0f - TINY) + TINY);
    float z = -logf(-logf(u)) + lg[i];
    if (z > best){ best = z; bi = i; }
  }
  float mx = lg[0];
  for (int i = 1; i < n; i++) mx = fmaxf(mx, lg[i]);
  float se = 0.f;
  for (int i = 0; i < n; i++) se += expf(lg[i] - mx);
  float lse = logf(se);
  d_lp += -(lg[bi] - mx - lse);
  float e = 0.f;
  for (int i = 0; i < n; i++){ float ls = lg[i] - mx - lse; e -= ls * expf(ls); }
  d_ent += e;
  return bi;
}

__device__ __forceinline__ float sigf(float x){ return 1.f / (1.f + expf(-x)); }

__device__ __forceinline__ float wdot(const float* __restrict__ w,
                                      const float* __restrict__ shv, int lane){
  const float4* w4 = (const float4*)w;
  const float4* h4 = (const float4*)shv;
  float a = 0.f;
#pragma unroll
  for (int t = 0; t < 16; t++){
    float4 wv = w4[lane + 32*t];
    float4 hv = h4[lane + 32*t];
    a += wv.x*hv.x + wv.y*hv.y + wv.z*hv.z + wv.w*hv.w;
  }
#pragma unroll
  for (int o = 16; o; o >>= 1) a += __shfl_xor_sync(0xffffffffu, a, o);
  return a;
}

// =====================================================================
// mega phase: one LSTM cell + optional merged work.
//   arow: -2 none, -1 aw1-only proj, >=0 anchor proj row (plus aw1)
//   attnL > 0: gate blocks emit attn partials for L anchors (from this
//              phase's input h); block 0 reduces+samples idx -> publishes
//   opsmp: block 0 computes op logits from input h, samples -> publishes
//   xrow >= 0 static input row; else consume published sample (seq sneed)
// =====================================================================
__device__ void mega(const P& p, float* sh, int b, int tid, int wi, int lane,
                     int gwa, int gwc, int hp,
                     int arow, int aidx,
                     int attnL,
                     int opsmp, int ub,
                     int xrow, unsigned sneed,
                     int arcpos, unsigned spub, unsigned aneed){
  // load input h (output of previous phase)
  for (int i = tid; i < H; i += NTH) sh[i] = __ldcg(&d_hb[hp][i]);
  __syncthreads();
  float* sp = sh + H;           // [WPB][16] attn partials
  float* sl = sh + H + 232;     // logits scratch
  int*   sx = (int*)(sh + H + 228);

  // ---- attn partials first (so block 0 can publish early) ----
  if (b > 0 && attnL > 0){
    if (gwc < H){
      float s = wdot(p.w2 + (size_t)gwc * H, sh, lane);
      if (lane == 0){
        float vt = p.v[gwc];
        for (int i = 0; i < attnL; i++)
          sp[wi*16 + i] = tanhf(__ldcg(&d_aw1[i][gwc]) + s) * vt;
      }
    } else if (lane == 0){
      for (int i = 0; i < attnL; i++) sp[wi*16 + i] = 0.f;
    }
    __syncthreads();
    if (tid == 0){
      for (int i = 0; i < attnL; i++){
        float s = 0.f;
#pragma unroll
        for (int w = 0; w < WPB; w++) s += sp[w*16 + i];
        d_blkpart[i][b-1] = s;
      }
      atomAddRel(&d_acnt, 1u);   // release: orders the partial stores above
    }
  }

  // ---- gate dots ----
  float a0=0.f, a1=0.f, a2=0.f, a3=0.f;
  bool gate = (b > 0) && (gwc < H);
  if (gate){
    int j = gwc;
    const float4* h4 = (const float4*)sh;
    const float4* w0 = (const float4*)(p.whh + (size_t)j        * H);
    const float4* w1 = (const float4*)(p.whh + (size_t)(j + H)  * H);
    const float4* w2 = (const float4*)(p.whh + (size_t)(j + 2*H)* H);
    const float4* w3 = (const float4*)(p.whh + (size_t)(j + 3*H)* H);
#pragma unroll
    for (int t = 0; t < 16; t++){
      float4 hv = h4[lane + 32*t];
      float4 x0 = w0[lane + 32*t];
      float4 x1 = w1[lane + 32*t];
      float4 x2 = w2[lane + 32*t];
      float4 x3 = w3[lane + 32*t];
      a0 += x0.x*hv.x + x0.y*hv.y + x0.z*hv.z + x0.w*hv.w;
      a1 += x1.x*hv.x + x1.y*hv.y + x1.z*hv.z + x1.w*hv.w;
      a2 += x2.x*hv.x + x2.y*hv.y + x2.z*hv.z + x2.w*hv.w;
      a3 += x3.x*hv.x + x3.y*hv.y + x3.z*hv.z + x3.w*hv.w;
    }
#pragma unroll
    for (int o = 16; o; o >>= 1){
      a0 += __shfl_xor_sync(0xffffffffu, a0, o);
      a1 += __shfl_xor_sync(0xffffffffu, a1, o);
      a2 += __shfl_xor_sync(0xffffffffu, a2, o);
      a3 += __shfl_xor_sync(0xffffffffu, a3, o);
    }
  }

  // ---- merged projection work (reads same input h) ----
  if (arow != -2){
    if (arow >= 0){
      for (int r = gwa; r < G; r += NW_ALL){
        float s = wdot(p.wih + (size_t)r * H, sh, lane);
        if (lane == 0) d_xproj[arow][r] = s;
      }
    }
    if (gwa < H){
      float s = wdot(p.w1 + (size_t)gwa * H, sh, lane);
      if (lane == 0) d_aw1[aidx][gwa] = s;
    }
  }

  // ---- block 0: sampling ----
  if (b == 0){
    if (attnL > 0){
      if (tid == 0){
        unsigned v;
        do { v = ldAcq(&d_acnt); } while ((int)(v - aneed) < 0);
      }
      __syncthreads();
      if (wi < attnL){
        float a = 0.f;
        for (int k = lane; k < NBLK-1; k += 32) a += __ldcg(&d_blkpart[wi][k]);
#pragma unroll
        for (int o = 16; o; o >>= 1) a += __shfl_xor_sync(0xffffffffu, a, o);
        if (lane == 0) sl[wi] = a;
      }
      __syncthreads();
      if (tid == 0){
        float lg[10];
        for (int i = 0; i < attnL; i++) lg[i] = 2.5f * tanhf(sl[i] / 5.0f);
        int idx = do_sample(attnL, lg);
        d_xrow = (idx < 2) ? 0 : (10 + idx - 2);
        p.out[arcpos] = (float)idx;
        stRel(&d_sflag, spub);
      }
    } else if (opsmp){
      if (wi < NBQ){
        float a = wdot(p.wsoft + (size_t)wi * H, sh, lane);
        if (lane == 0) sl[wi] = a;
      }
      __syncthreads();
      if (tid == 0){
        float lg[NBQ];
        for (int i = 0; i < NBQ; i++){
          lg[i] = tanhf((sl[i] + p.bsoft[i]) / 5.0f);
          if (ub) lg[i] += p.bsnl[i];
        }
        int op = do_sample(NBQ, lg);
        d_xrow = 2 + op;
        p.out[arcpos] = (float)op;
        stRel(&d_sflag, spub);
      }
    }
  }

  // ---- gate add (consume sample if dynamic) ----
  if (b > 0){
    int xr = xrow;
    if (xrow < 0){
      __syncthreads();
      if (tid == 0){
        unsigned v;
        do { v = ldAcq(&d_sflag); } while ((int)(v - sneed) < 0);
        sx[0] = *((volatile int*)&d_xrow);
      }
      __syncthreads();
      xr = sx[0];
    }
    if (gate && lane == 0){
      int j = gwc;
      const float* xp = d_xproj[xr];
      float gi = a0 + __ldcg(xp + j)       + d_bsum[j];
      float gf = a1 + __ldcg(xp + j + H)   + d_bsum[j + H];
      float gg = a2 + __ldcg(xp + j + 2*H) + d_bsum[j + 2*H];
      float go = a3 + __ldcg(xp + j + 3*H) + d_bsum[j + 3*H];
      float c2 = sigf(gf) * d_c[j] + sigf(gi) * tanhf(gg);
      float h2 = sigf(go) * tanhf(c2);
      d_c[j] = c2;
      d_hb[hp ^ 1][j] = h2;
    }
  }
}

__global__ void __launch_bounds__(NTH, 1) ctrl_kernel(P p){
  extern __shared__ float sh[];
  int tid = threadIdx.x, wi = tid >> 5, lane = tid & 31;
  int b = blockIdx.x;
  unsigned gen   = *((volatile unsigned*)&g_flag);
  unsigned sbase = *((volatile unsigned*)&d_sflag);
  unsigned abase = *((volatile unsigned*)&d_acnt);
  unsigned sc = 0, na = 0;
  int gwa = b * WPB + wi;
  int gwc = (b == 0) ? H : (b - 1) * WPB + wi;

  // ---- init ----
  for (int i = b*NTH + tid; i < H; i += NBLK*NTH){
    d_c[i] = 0.f; d_hb[0][i] = 0.f; d_hb[1][i] = 0.f;
  }
  for (int i = b*NTH + tid; i < G; i += NBLK*NTH){
    d_bsum[i] = p.bih[i] + p.bhh[i];
    d_xproj[0][i] = 0.f;
  }
  if (b == 0 && tid == 0){
    d_k0 = 0u; d_k1 = 42u;
    d_lp = 0.f; d_ent = 0.f;
  }
  for (int i = tid; i < 9*H; i += NTH) sh[i] = p.enc[i];
  __syncthreads();
  for (int r = gwa; r < G; r += NW_ALL){
    const float4* w4 = (const float4*)(p.wih + (size_t)r * H);
    float acc[9];
#pragma unroll
    for (int e = 0; e < 9; e++) acc[e] = 0.f;
    for (int t = 0; t < 16; t++){
      float4 wv = w4[lane + 32*t];
#pragma unroll
      for (int e = 0; e < 9; e++){
        float4 xv = ((const float4*)sh)[e*512 + lane + 32*t];
        acc[e] += wv.x*xv.x + wv.y*xv.y + wv.z*xv.z + wv.w*xv.w;
      }
    }
    for (int e = 0; e < 9; e++){
      float a = acc[e];
#pragma unroll
      for (int o = 16; o; o >>= 1) a += __shfl_xor_sync(0xffffffffu, a, o);
      if (lane == 0) d_xproj[1 + e][r] = a;
    }
  }
  gsync(gen);

  // ---- two sampler runs, 42 phases each ----
  int hp = 0;
  int p_ar = -2, p_ai = 0;   // pending projection
  for (int smp = 0; smp < 2; smp++){
    int ab = smp * 32;
    int ub = (smp == 0);
    // init cell 0 (+ pending anchor proj from previous sampler)
    mega(p, sh, b, tid, wi, lane, gwa, gwc, hp, p_ar, p_ai, 0, 0, 0, 1, 0, 0, 0, 0);
    hp ^= 1; gsync(gen);
    p_ar = -1; p_ai = 0;
    // init cell 1 (+ aw1[0] proj)
    mega(p, sh, b, tid, wi, lane, gwa, gwc, hp, p_ar, p_ai, 0, 0, 0, 1, 0, 0, 0, 0);
    hp ^= 1; gsync(gen);
    p_ar = -1; p_ai = 1;
    for (int L = 2; L <= 9; L++){
      int base = ab + (L - 2) * 4;
      // ph1: cell_idx0 (enc0) + pending proj
      mega(p, sh, b, tid, wi, lane, gwa, gwc, hp, p_ar, p_ai, 0, 0, 0, 1, 0, 0, 0, 0);
      hp ^= 1; gsync(gen);
      // ph2: cell_idx1 + attn(h1) ; b0 samples idx0
      sc++; na++;
      mega(p, sh, b, tid, wi, lane, gwa, gwc, hp, -2, 0, L, 0, 0, -1, sbase + sc,
           base + 0, sbase + sc, abase + (NBLK-1)*na);
      hp ^= 1; gsync(gen);
      // ph3: cell_op0 + attn(h2) ; b0 samples idx1
      sc++; na++;
      mega(p, sh, b, tid, wi, lane, gwa, gwc, hp, -2, 0, L, 0, 0, -1, sbase + sc,
           base + 2, sbase + sc, abase + (NBLK-1)*na);
      hp ^= 1; gsync(gen);
      // ph4: cell_op1 ; b0 samples op0 from h3
      sc++;
      mega(p, sh, b, tid, wi, lane, gwa, gwc, hp, -2, 0, 0, 1, ub, -1, sbase + sc,
           base + 1, sbase + sc, 0);
      hp ^= 1; gsync(gen);
      // ph5: cell_anchor ; b0 samples op1 from h4
      sc++;
      mega(p, sh, b, tid, wi, lane, gwa, gwc, hp, -2, 0, 0, 1, ub, -1, sbase + sc,
           base + 3, sbase + sc, 0);
      hp ^= 1; gsync(gen);
      p_ar = 10 + (L - 2); p_ai = L;
    }
  }

  if (b == 0 && tid == 0){
    p.out[64] = d_lp;
    p.out[65] = d_ent;
  }
}

extern "C" void kernel_launch(void* const* d_in, const int* in_sizes, int n_in,
                              void* d_out, int out_size){
  P p;
  p.enc   = (const float*)d_in[0];
  p.wih   = (const float*)d_in[1];
  p.bih   = (const float*)d_in[2];
  p.whh   = (const float*)d_in[3];
  p.bhh   = (const float*)d_in[4];
  p.wsoft = (const float*)d_in[5];
  p.bsoft = (const float*)d_in[6];
  p.bsnl  = (const float*)d_in[7];
  p.w1    = (const float*)d_in[8];
  p.w2    = (const float*)d_in[9];
  p.v     = (const float*)d_in[10];
  p.out   = (float*)d_out;
  (void)in_sizes; (void)n_in; (void)out_size;

  size_t smem = 9 * H * sizeof(float);
  cudaFuncSetAttribute(ctrl_kernel, cudaFuncAttributeMaxDynamicSharedMemorySize, (int)smem);
  ctrl_kernel<<<NBLK, NTH, smem>>>(p);
}